// round 1
// baseline (speedup 1.0000x reference)
#include <cuda_runtime.h>
#include <math.h>

// ---------------------------------------------------------------------------
// Problem shapes (fixed):
//   sparse_fea [64,256,64]  dense_fea [64,128,4096]  stk_coor [64,64,32]
//   conv_w [256,128,1,3]    conv_b[256](=0, cancels) bn_gamma/beta [256]
// Output concat: sparse_out [64,256,32] | dense_out [64,256,1024] | coor [64,32,32]
// ---------------------------------------------------------------------------

#define OFF_DENSE 524288
#define OFF_COOR  (524288 + 16777216)

__device__ int   g_fps_idx[64 * 32];
__device__ float g_y[64 * 256 * 1024];   // conv output scratch (67MB)
__device__ float g_mean[256];
__device__ float g_rstd[256];

// ---------------------------------------------------------------------------
// FPS: one block per batch, 64 threads (one per point). Warp-shuffle argmax
// with first-index tie-break (matches jnp.argmax).
// ---------------------------------------------------------------------------
__global__ void fps_kernel(const float* __restrict__ stk_coor,
                           float* __restrict__ out_coor)
{
    int b = blockIdx.x;
    int t = threadIdx.x;                     // 0..63

    __shared__ float coor[64][33];           // padded: avoid 32-way conflicts
    __shared__ float sdist[64];
    __shared__ int   sidx[32];
    __shared__ int   s_far;

    #pragma unroll
    for (int c = 0; c < 32; c++)
        coor[t][c] = stk_coor[(b * 64 + t) * 32 + c];
    if (t == 0) s_far = 0;
    float dist = 1e10f;
    __syncthreads();

    for (int i = 0; i < 32; i++) {
        int far = s_far;
        if (t == 0) sidx[i] = far;
        float d = 0.f;
        #pragma unroll
        for (int c = 0; c < 32; c++) {
            float df = coor[t][c] - coor[far][c];
            d += df * df;
        }
        dist = fminf(dist, d);
        sdist[t] = dist;
        __syncthreads();
        if (t < 32) {
            float bv = sdist[t];       int bi = t;
            float v2 = sdist[t + 32];
            if (v2 > bv) { bv = v2; bi = t + 32; }
            #pragma unroll
            for (int off = 16; off > 0; off >>= 1) {
                float ov = __shfl_down_sync(0xffffffffu, bv, off);
                int   oi = __shfl_down_sync(0xffffffffu, bi, off);
                if (ov > bv || (ov == bv && oi < bi)) { bv = ov; bi = oi; }
            }
            if (t == 0) s_far = bi;
        }
        __syncthreads();
    }

    if (t < 32) g_fps_idx[b * 32 + t] = sidx[t];
    for (int v = t; v < 32 * 32; v += 64) {
        int i = v >> 5, c = v & 31;
        out_coor[(b * 32 + i) * 32 + c] = coor[sidx[i]][c];
    }
}

// ---------------------------------------------------------------------------
// sparse_out[b,e,s] = sparse_fea[b,e,idx[b,s]]
// ---------------------------------------------------------------------------
__global__ void gather_sparse(const float* __restrict__ sp,
                              float* __restrict__ out)
{
    int t = blockIdx.x * 256 + threadIdx.x;     // < 524288
    int b = t >> 13;
    int r = t & 8191;
    int e = r >> 5;
    int s = r & 31;
    out[t] = sp[(size_t)(b * 256 + e) * 64 + g_fps_idx[b * 32 + s]];
}

// ---------------------------------------------------------------------------
// Conv (1,3) stride (1,2) pad (1,1), 128->256 ch, fused gather of 2 strokes
// per block. grid (16 stroke-pairs, 64 batches), 256 threads.
// Thread tile: 8 co x 8 q (64 acc regs). co = cg + 32*j (cg = lane) so weight
// LDS.128 is coalesced; x loads are warp-broadcast. Epilogue transposes
// through padded smem for coalesced STG.
// smem: xs[2][128][72] (73728B) + ws4[16][256] float4 (65536B) = 139264B
// ---------------------------------------------------------------------------
__global__ void __launch_bounds__(256, 1)
conv_kernel(const float* __restrict__ dense, const float* __restrict__ w)
{
    extern __shared__ float smem[];
    float*  xs  = smem;                                // 2*128*72 floats
    float4* ws4 = (float4*)(smem + 2 * 128 * 72);      // 16*256 float4

    int b  = blockIdx.y;
    int sp = blockIdx.x;                               // stroke pair 0..15
    int t  = threadIdx.x;
    int s_local = t >> 7;                              // 0..1
    int u  = t & 127;
    int qg = u >> 5;                                   // 0..3 -> q base 8*qg
    int cg = u & 31;                                   // lane

    __shared__ int stk[2];
    if (t < 2) stk[t] = g_fps_idx[b * 32 + sp * 2 + t];

    // zero pads: each of 256 rows handled by one thread
    xs[t * 72 + 0]  = 0.f;
    xs[t * 72 + 65] = 0.f;
    xs[t * 72 + 66] = 0.f;
    xs[t * 72 + 67] = 0.f;
    __syncthreads();

    // gather input tile: 2 strokes x 128 cin x 64 p (float4 granularity)
    for (int v = t; v < 4096; v += 256) {
        int sl  = v >> 11;
        int rem = v & 2047;
        int cin = rem >> 4;
        int pv  = rem & 15;
        float4 s4 = *(const float4*)&dense[(size_t)(b * 128 + cin) * 4096 +
                                           stk[sl] * 64 + pv * 4];
        float* dst = &xs[(sl * 128 + cin) * 72 + 1 + pv * 4];
        dst[0] = s4.x; dst[1] = s4.y; dst[2] = s4.z; dst[3] = s4.w;
    }

    float acc[64];
    #pragma unroll
    for (int i = 0; i < 64; i++) acc[i] = 0.f;

    for (int ch = 0; ch < 8; ch++) {                   // cin chunks of 16
        __syncthreads();
        for (int v = t; v < 4096; v += 256) {          // stage weights
            int co = v >> 4, kc = v & 15;
            const float* gw = &w[co * 384 + (ch * 16 + kc) * 3];
            ws4[kc * 256 + co] = make_float4(gw[0], gw[1], gw[2], 0.f);
        }
        __syncthreads();

        #pragma unroll
        for (int kc = 0; kc < 16; kc++) {
            const float* xr = &xs[(s_local * 128 + ch * 16 + kc) * 72 + 16 * qg];
            float xv[17];
            #pragma unroll
            for (int i = 0; i < 4; i++) {
                float4 a = *(const float4*)(xr + 4 * i);
                xv[4 * i]     = a.x;
                xv[4 * i + 1] = a.y;
                xv[4 * i + 2] = a.z;
                xv[4 * i + 3] = a.w;
            }
            xv[16] = xr[16];
            #pragma unroll
            for (int j = 0; j < 8; j++) {
                float4 wv = ws4[kc * 256 + j * 32 + cg];
                #pragma unroll
                for (int qi = 0; qi < 8; qi++) {
                    acc[j * 8 + qi] =
                        fmaf(wv.x, xv[2 * qi],
                        fmaf(wv.y, xv[2 * qi + 1],
                        fmaf(wv.z, xv[2 * qi + 2], acc[j * 8 + qi])));
                }
            }
        }
    }
    __syncthreads();

    // epilogue: smem transpose (reuse smem), then coalesced STG
    float* ys = smem;                                  // [2][256][33]
    #pragma unroll
    for (int j = 0; j < 8; j++) {
        int co = j * 32 + cg;
        #pragma unroll
        for (int qi = 0; qi < 8; qi++)
            ys[(s_local * 256 + co) * 33 + qg * 8 + qi] = acc[j * 8 + qi];
    }
    __syncthreads();

    int wid = t >> 5, lane = t & 31;
    for (int r = wid; r < 512; r += 8) {
        int sl = r >> 8, co = r & 255;
        g_y[((size_t)(b * 256 + co) * 32 + (sp * 2 + sl)) * 32 + lane] =
            ys[r * 33 + lane];
    }
}

// ---------------------------------------------------------------------------
// BN batch stats: one block per channel over 64*1024 values.
// ---------------------------------------------------------------------------
__global__ void bn_stats_kernel()
{
    int co = blockIdx.x;
    int t  = threadIdx.x;                              // 256
    float s = 0.f, sq = 0.f;
    for (int v = t; v < 65536; v += 256) {
        float y = g_y[(size_t)(v >> 10) * 262144 + co * 1024 + (v & 1023)];
        s  += y;
        sq += y * y;
    }
    __shared__ float rs[256], rq[256];
    rs[t] = s; rq[t] = sq;
    __syncthreads();
    for (int st = 128; st > 0; st >>= 1) {
        if (t < st) { rs[t] += rs[t + st]; rq[t] += rq[t + st]; }
        __syncthreads();
    }
    if (t == 0) {
        float mean = rs[0] * (1.f / 65536.f);
        float var  = rq[0] * (1.f / 65536.f) - mean * mean;
        g_mean[co] = mean;
        g_rstd[co] = rsqrtf(var + 1e-5f);
    }
}

// ---------------------------------------------------------------------------
// Normalize + scale/shift + tanh-GELU (matches jax.nn.gelu approximate=True)
// ---------------------------------------------------------------------------
__global__ void bn_gelu_kernel(const float* __restrict__ gamma,
                               const float* __restrict__ beta,
                               float* __restrict__ out)
{
    int i  = blockIdx.x * 256 + threadIdx.x;           // < 16777216
    int co = (i >> 10) & 255;
    float x = (g_y[i] - g_mean[co]) * g_rstd[co] * gamma[co] + beta[co];
    float u = 0.7978845608028654f * (x + 0.044715f * x * x * x);
    out[i]  = 0.5f * x * (1.f + tanhf(u));
}

// ---------------------------------------------------------------------------
extern "C" void kernel_launch(void* const* d_in, const int* in_sizes, int n_in,
                              void* d_out, int out_size)
{
    const float* sparse_fea = (const float*)d_in[0];
    const float* dense_fea  = (const float*)d_in[1];
    const float* stk_coor   = (const float*)d_in[2];
    const float* conv_w     = (const float*)d_in[3];
    // d_in[4] = conv_b: zeros AND provably cancels under batch-stat BN.
    const float* bn_gamma   = (const float*)d_in[5];
    const float* bn_beta    = (const float*)d_in[6];
    float* out = (float*)d_out;

    cudaFuncSetAttribute(conv_kernel,
                         cudaFuncAttributeMaxDynamicSharedMemorySize, 139264);

    fps_kernel<<<64, 64>>>(stk_coor, out + OFF_COOR);
    gather_sparse<<<2048, 256>>>(sparse_fea, out);
    conv_kernel<<<dim3(16, 64), 256, 139264>>>(dense_fea, conv_w);
    bn_stats_kernel<<<256, 256>>>();
    bn_gelu_kernel<<<65536, 256>>>(bn_gamma, bn_beta, out + OFF_DENSE);
}

// round 2
// speedup vs baseline: 3.2763x; 3.2763x over previous
#include <cuda_runtime.h>
#include <math.h>
#include <stdint.h>

// ---------------------------------------------------------------------------
// Shapes: sparse_fea[64,256,64] dense_fea[64,128,4096] stk_coor[64,64,32]
//         conv_w[256,128,3] (flat [256][384]) bn_gamma/beta[256]
// Output: sparse_out[64,256,32] | dense_out[64,256,1024] | coor[64,32,32]
// ---------------------------------------------------------------------------

#define OFF_DENSE 524288
#define OFF_COOR  (524288 + 16777216)

__device__ int   g_fps_idx[64 * 32];
__device__ float g_y[64 * 256 * 1024];   // conv output scratch
__device__ float g_sum[256];
__device__ float g_sqsum[256];
__device__ float g_mean[256];
__device__ float g_rstd[256];

__device__ __forceinline__ unsigned smem_addr(const void* p) {
    return (unsigned)__cvta_generic_to_shared(p);
}
__device__ __forceinline__ void cp_async16(unsigned dst, const void* src) {
    asm volatile("cp.async.cg.shared.global [%0], [%1], 16;\n" :: "r"(dst), "l"(src));
}
__device__ __forceinline__ uint32_t f2tf32(float f) {
    uint32_t u;
    asm("cvt.rna.tf32.f32 %0, %1;" : "=r"(u) : "f"(f));
    return u;
}
__device__ __forceinline__ void mma_tf32(float c[4], const uint32_t a[4],
                                         uint32_t b0, uint32_t b1) {
    asm volatile(
        "mma.sync.aligned.m16n8k8.row.col.f32.tf32.tf32.f32 "
        "{%0,%1,%2,%3},{%4,%5,%6,%7},{%8,%9},{%0,%1,%2,%3};"
        : "+f"(c[0]), "+f"(c[1]), "+f"(c[2]), "+f"(c[3])
        : "r"(a[0]), "r"(a[1]), "r"(a[2]), "r"(a[3]), "r"(b0), "r"(b1));
}

// ---------------------------------------------------------------------------
// FPS: one block per batch, 64 threads. Also zeroes BN accumulators (block 0).
// ---------------------------------------------------------------------------
__global__ void fps_kernel(const float* __restrict__ stk_coor,
                           float* __restrict__ out_coor)
{
    int b = blockIdx.x;
    int t = threadIdx.x;                     // 0..63

    if (b == 0) {
        for (int i = t; i < 256; i += 64) { g_sum[i] = 0.f; g_sqsum[i] = 0.f; }
    }

    __shared__ float coor[64][33];
    __shared__ float sdist[64];
    __shared__ int   sidx[32];
    __shared__ int   s_far;

    #pragma unroll
    for (int c = 0; c < 32; c++)
        coor[t][c] = stk_coor[(b * 64 + t) * 32 + c];
    if (t == 0) s_far = 0;
    float dist = 1e10f;
    __syncthreads();

    for (int i = 0; i < 32; i++) {
        int far = s_far;
        if (t == 0) sidx[i] = far;
        float d = 0.f;
        #pragma unroll
        for (int c = 0; c < 32; c++) {
            float df = coor[t][c] - coor[far][c];
            d += df * df;
        }
        dist = fminf(dist, d);
        sdist[t] = dist;
        __syncthreads();
        if (t < 32) {
            float bv = sdist[t];       int bi = t;
            float v2 = sdist[t + 32];
            if (v2 > bv) { bv = v2; bi = t + 32; }
            #pragma unroll
            for (int off = 16; off > 0; off >>= 1) {
                float ov = __shfl_down_sync(0xffffffffu, bv, off);
                int   oi = __shfl_down_sync(0xffffffffu, bi, off);
                if (ov > bv || (ov == bv && oi < bi)) { bv = ov; bi = oi; }
            }
            if (t == 0) s_far = bi;
        }
        __syncthreads();
    }

    if (t < 32) g_fps_idx[b * 32 + t] = sidx[t];
    for (int v = t; v < 32 * 32; v += 64) {
        int i = v >> 5, c = v & 31;
        out_coor[(b * 32 + i) * 32 + c] = coor[sidx[i]][c];
    }
}

// ---------------------------------------------------------------------------
// sparse_out[b,e,s] = sparse_fea[b,e,idx[b,s]]
// ---------------------------------------------------------------------------
__global__ void gather_sparse(const float* __restrict__ sp,
                              float* __restrict__ out)
{
    int t = blockIdx.x * 256 + threadIdx.x;     // < 524288
    int b = t >> 13;
    int r = t & 8191;
    int e = r >> 5;
    int s = r & 31;
    out[t] = sp[(size_t)(b * 256 + e) * 64 + g_fps_idx[b * 32 + s]];
}

// ---------------------------------------------------------------------------
// tf32 tensor-core conv-as-GEMM.
// Block: 256 thr. Tile M=128 (co half) x N=256 (8 strokes x 32 q), K=384.
// K streamed in 16 chunks of 24 (8 cin x 3 taps), cp.async double-buffered.
// smem pipeline layout (floats):
//   ws[buf] : 128 x 28   at 0 / 3584      (weights, [co][k24], conflict-free)
//   xs[buf] : 8cl x 8s x 72 at 7168/11776 (raw rows, p stored at idx 4..67,
//                                          zeros at idx 3 and 68)
// Epilogue reuses smem as ys[64][268] for coalesced stores; BN sum/sumsq
// fused via atomics.
// ---------------------------------------------------------------------------
__device__ __forceinline__ void stage_chunk(
    float* smem, int c, int buf, int t, int b, int co0,
    const int* stk, const float* __restrict__ dense, const float* __restrict__ w)
{
    float* xb = smem + 7168 + buf * 4608;
    float* wb = smem + buf * 3584;
    #pragma unroll
    for (int i = 0; i < 4; i++) {
        int v = t + 256 * i;          // 0..1023
        int row = v >> 4, j = v & 15;
        int cl = row >> 3, s = row & 7;
        const float* src = dense + ((size_t)(b * 128 + c * 8 + cl) * 4096 +
                                    (size_t)stk[s] * 64 + j * 4);
        cp_async16(smem_addr(xb + row * 72 + 4 + j * 4), src);
    }
    #pragma unroll
    for (int i = 0; i < 3; i++) {
        int v = t + 256 * i;          // 0..767
        int co = v / 6, seg = v - co * 6;
        const float* src = w + ((size_t)(co0 + co) * 384 + c * 24 + seg * 4);
        cp_async16(smem_addr(wb + co * 28 + seg * 4), src);
    }
}

__global__ void __launch_bounds__(256, 1)
conv_mma_kernel(const float* __restrict__ dense, const float* __restrict__ w)
{
    extern __shared__ float smem[];

    const int b    = blockIdx.y;
    const int ch   = blockIdx.x & 1;       // co half
    const int sgrp = blockIdx.x >> 1;      // 0..3
    const int co0  = ch * 128;
    const int t    = threadIdx.x;
    const int wp   = t >> 5;
    const int lane = t & 31;
    const int g    = lane >> 2;            // fragment group row
    const int tig  = lane & 3;             // thread-in-group
    const int wm   = wp & 1;
    const int wn   = wp >> 1;
    const int m_warp = wm * 64;
    const int n_warp = wn * 64;

    __shared__ int stk[8];
    if (t < 8) stk[t] = g_fps_idx[b * 32 + sgrp * 8 + t];
    if (t < 128) {                         // zero pad cols of both xs buffers
        int bi = t >> 6, r = t & 63;
        float* xb = smem + 7168 + bi * 4608;
        xb[r * 72 + 3]  = 0.f;
        xb[r * 72 + 68] = 0.f;
    }
    __syncthreads();

    stage_chunk(smem, 0, 0, t, b, co0, stk, dense, w);
    asm volatile("cp.async.commit_group;");
    asm volatile("cp.async.wait_group 0;");
    __syncthreads();

    // per-thread fragment addressing
    const int abase = (m_warp + g) * 28 + tig;
    int bn_base[8];
    #pragma unroll
    for (int nf = 0; nf < 8; nf++) {
        int n = n_warp + nf * 8 + g;       // B-fragment column index
        bn_base[nf] = (n >> 5) * 72 + 2 * (n & 31) + 3;
    }
    int bk[3][2];
    #pragma unroll
    for (int ks = 0; ks < 3; ks++)
        #pragma unroll
        for (int h = 0; h < 2; h++) {
            int k = ks * 8 + tig + 4 * h;  // k < 24
            int cl = (k * 11) >> 5;        // k / 3
            bk[ks][h] = cl * 576 + (k - 3 * cl);
        }

    float acc[4][8][4];
    #pragma unroll
    for (int mf = 0; mf < 4; mf++)
        #pragma unroll
        for (int nf = 0; nf < 8; nf++)
            #pragma unroll
            for (int i = 0; i < 4; i++) acc[mf][nf][i] = 0.f;

    for (int c = 0; c < 16; ++c) {
        int pb = c & 1;
        if (c + 1 < 16) stage_chunk(smem, c + 1, pb ^ 1, t, b, co0, stk, dense, w);
        asm volatile("cp.async.commit_group;");

        const float* wsb = smem + (pb ? 3584 : 0);
        const float* xsb = smem + 7168 + (pb ? 4608 : 0);
        #pragma unroll
        for (int ks = 0; ks < 3; ks++) {
            uint32_t A[4][4];
            #pragma unroll
            for (int mf = 0; mf < 4; mf++) {
                int ai = abase + mf * 448 + ks * 8;
                A[mf][0] = f2tf32(wsb[ai]);          // (row g,   k)
                A[mf][1] = f2tf32(wsb[ai + 224]);    // (row g+8, k)
                A[mf][2] = f2tf32(wsb[ai + 4]);      // (row g,   k+4)
                A[mf][3] = f2tf32(wsb[ai + 228]);    // (row g+8, k+4)
            }
            #pragma unroll
            for (int nf = 0; nf < 8; nf++) {
                uint32_t B0 = f2tf32(xsb[bn_base[nf] + bk[ks][0]]);
                uint32_t B1 = f2tf32(xsb[bn_base[nf] + bk[ks][1]]);
                #pragma unroll
                for (int mf = 0; mf < 4; mf++)
                    mma_tf32(acc[mf][nf], A[mf], B0, B1);
            }
        }
        asm volatile("cp.async.wait_group 0;");
        __syncthreads();
    }

    // --- fused BN partial sums (reduce over tig lanes, atomics per channel)
    #pragma unroll
    for (int mf = 0; mf < 4; mf++) {
        float s0 = 0.f, q0 = 0.f, s1 = 0.f, q1 = 0.f;
        #pragma unroll
        for (int nf = 0; nf < 8; nf++) {
            float c0 = acc[mf][nf][0], c1 = acc[mf][nf][1];
            float c2 = acc[mf][nf][2], c3 = acc[mf][nf][3];
            s0 += c0 + c1;  q0 += c0 * c0 + c1 * c1;
            s1 += c2 + c3;  q1 += c2 * c2 + c3 * c3;
        }
        #pragma unroll
        for (int off = 1; off < 4; off <<= 1) {
            s0 += __shfl_xor_sync(0xffffffffu, s0, off);
            q0 += __shfl_xor_sync(0xffffffffu, q0, off);
            s1 += __shfl_xor_sync(0xffffffffu, s1, off);
            q1 += __shfl_xor_sync(0xffffffffu, q1, off);
        }
        if (tig == 0) {
            int co = co0 + m_warp + mf * 16 + g;
            atomicAdd(&g_sum[co],       s0);
            atomicAdd(&g_sqsum[co],     q0);
            atomicAdd(&g_sum[co + 8],   s1);
            atomicAdd(&g_sqsum[co + 8], q1);
        }
    }

    // --- epilogue: two-phase smem transpose (64 co x 256 n), coalesced STG
    float* ys = smem;                      // [64][268]
    #pragma unroll
    for (int ph = 0; ph < 2; ph++) {
        __syncthreads();
        if (wm == ph) {
            #pragma unroll
            for (int mf = 0; mf < 4; mf++)
                #pragma unroll
                for (int nf = 0; nf < 8; nf++) {
                    int row = mf * 16 + g;
                    int nC  = n_warp + nf * 8 + 2 * tig;   // C col = 2*tig
                    *(float2*)&ys[row * 268 + nC] =
                        make_float2(acc[mf][nf][0], acc[mf][nf][1]);
                    *(float2*)&ys[(row + 8) * 268 + nC] =
                        make_float2(acc[mf][nf][2], acc[mf][nf][3]);
                }
        }
        __syncthreads();
        int row = t >> 2, jb = t & 3;
        float* dst = g_y + ((size_t)(b * 256 + co0 + ph * 64 + row)) * 1024 +
                     sgrp * 256;
        #pragma unroll
        for (int jj = 0; jj < 16; jj++) {
            int j = jb + jj * 4;
            *(float4*)(dst + j * 4) = *(const float4*)&ys[row * 268 + j * 4];
        }
    }
}

// ---------------------------------------------------------------------------
// mean/rstd from fused sums
// ---------------------------------------------------------------------------
__global__ void bn_finalize_kernel()
{
    int t = threadIdx.x;                   // 256
    float mean = g_sum[t] * (1.f / 65536.f);
    float var  = g_sqsum[t] * (1.f / 65536.f) - mean * mean;
    g_mean[t] = mean;
    g_rstd[t] = rsqrtf(var + 1e-5f);
}

// ---------------------------------------------------------------------------
// Normalize + scale/shift + tanh-GELU, float4 vectorized
// ---------------------------------------------------------------------------
__global__ void bn_gelu_kernel(const float* __restrict__ gamma,
                               const float* __restrict__ beta,
                               float* __restrict__ out)
{
    int i4 = blockIdx.x * 256 + threadIdx.x;   // < 4194304
    int co = (i4 >> 8) & 255;
    float m  = g_mean[co];
    float ga = g_rstd[co] * gamma[co];
    float be = beta[co];
    float4 v = *(const float4*)&g_y[(size_t)i4 * 4];
    float4 r;
    {
        float x = (v.x - m) * ga + be;
        float u = 0.7978845608028654f * (x + 0.044715f * x * x * x);
        r.x = 0.5f * x * (1.f + tanhf(u));
    }
    {
        float x = (v.y - m) * ga + be;
        float u = 0.7978845608028654f * (x + 0.044715f * x * x * x);
        r.y = 0.5f * x * (1.f + tanhf(u));
    }
    {
        float x = (v.z - m) * ga + be;
        float u = 0.7978845608028654f * (x + 0.044715f * x * x * x);
        r.z = 0.5f * x * (1.f + tanhf(u));
    }
    {
        float x = (v.w - m) * ga + be;
        float u = 0.7978845608028654f * (x + 0.044715f * x * x * x);
        r.w = 0.5f * x * (1.f + tanhf(u));
    }
    *(float4*)&out[(size_t)i4 * 4] = r;
}

// ---------------------------------------------------------------------------
extern "C" void kernel_launch(void* const* d_in, const int* in_sizes, int n_in,
                              void* d_out, int out_size)
{
    const float* sparse_fea = (const float*)d_in[0];
    const float* dense_fea  = (const float*)d_in[1];
    const float* stk_coor   = (const float*)d_in[2];
    const float* conv_w     = (const float*)d_in[3];
    // d_in[4] = conv_b: zeros AND cancels under batch-stat BN.
    const float* bn_gamma   = (const float*)d_in[5];
    const float* bn_beta    = (const float*)d_in[6];
    float* out = (float*)d_out;

    cudaFuncSetAttribute(conv_mma_kernel,
                         cudaFuncAttributeMaxDynamicSharedMemorySize, 68608);

    fps_kernel<<<64, 64>>>(stk_coor, out + OFF_COOR);
    gather_sparse<<<2048, 256>>>(sparse_fea, out);
    conv_mma_kernel<<<dim3(8, 64), 256, 68608>>>(dense_fea, conv_w);
    bn_finalize_kernel<<<1, 256>>>();
    bn_gelu_kernel<<<16384, 256>>>(bn_gamma, bn_beta, out + OFF_DENSE);
}

// round 3
// speedup vs baseline: 3.6149x; 1.1033x over previous
#include <cuda_runtime.h>
#include <math.h>
#include <stdint.h>

// ---------------------------------------------------------------------------
// Shapes: sparse_fea[64,256,64] dense_fea[64,128,4096] stk_coor[64,64,32]
//         conv_w[256,128,3] (flat [256][384]) bn_gamma/beta[256]
// Output: sparse_out[64,256,32] | dense_out[64,256,1024] | coor[64,32,32]
// ---------------------------------------------------------------------------

#define OFF_DENSE 524288
#define OFF_COOR  (524288 + 16777216)

__device__ int      g_fps_idx[64 * 32];
__device__ float    g_y[64 * 256 * 1024];     // conv output scratch
__device__ float    g_sum[256];
__device__ float    g_sqsum[256];
__device__ uint32_t g_wt[256 * 384];          // tf32 weights, tap-major per chunk

__device__ __forceinline__ unsigned smem_addr(const void* p) {
    return (unsigned)__cvta_generic_to_shared(p);
}
__device__ __forceinline__ void cp_async16(unsigned dst, const void* src) {
    asm volatile("cp.async.cg.shared.global [%0], [%1], 16;\n" :: "r"(dst), "l"(src));
}
__device__ __forceinline__ uint32_t f2tf32(float f) {
    uint32_t u;
    asm("cvt.rna.tf32.f32 %0, %1;" : "=r"(u) : "f"(f));
    return u;
}
__device__ __forceinline__ void mma_tf32(float c[4], const uint32_t a[4],
                                         uint32_t b0, uint32_t b1) {
    asm volatile(
        "mma.sync.aligned.m16n8k8.row.col.f32.tf32.tf32.f32 "
        "{%0,%1,%2,%3},{%4,%5,%6,%7},{%8,%9},{%0,%1,%2,%3};"
        : "+f"(c[0]), "+f"(c[1]), "+f"(c[2]), "+f"(c[3])
        : "r"(a[0]), "r"(a[1]), "r"(a[2]), "r"(a[3]), "r"(b0), "r"(b1));
}

// ---------------------------------------------------------------------------
// Weight prep: reorder to [co][chunk16][tap3][cl8], pre-convert to tf32.
// ---------------------------------------------------------------------------
__global__ void wprep_kernel(const float* __restrict__ w)
{
    int co = blockIdx.x;                 // 256
    int r  = threadIdx.x;                // 384
    int c   = r / 24;
    int q2  = r - c * 24;
    int tap = q2 >> 3;
    int cl  = q2 & 7;
    g_wt[co * 384 + r] = f2tf32(w[co * 384 + (c * 8 + cl) * 3 + tap]);
}

// ---------------------------------------------------------------------------
// FPS: one block per batch, 64 threads. Block 0 zeroes BN accumulators.
// ---------------------------------------------------------------------------
__global__ void fps_kernel(const float* __restrict__ stk_coor,
                           float* __restrict__ out_coor)
{
    int b = blockIdx.x;
    int t = threadIdx.x;                     // 0..63

    if (b == 0) {
        for (int i = t; i < 256; i += 64) { g_sum[i] = 0.f; g_sqsum[i] = 0.f; }
    }

    __shared__ float coor[64][33];
    __shared__ float sdist[64];
    __shared__ int   sidx[32];
    __shared__ int   s_far;

    #pragma unroll
    for (int c = 0; c < 32; c++)
        coor[t][c] = stk_coor[(b * 64 + t) * 32 + c];
    if (t == 0) s_far = 0;
    float dist = 1e10f;
    __syncthreads();

    for (int i = 0; i < 32; i++) {
        int far = s_far;
        if (t == 0) sidx[i] = far;
        float d = 0.f;
        #pragma unroll
        for (int c = 0; c < 32; c++) {
            float df = coor[t][c] - coor[far][c];
            d += df * df;
        }
        dist = fminf(dist, d);
        sdist[t] = dist;
        __syncthreads();
        if (t < 32) {
            float bv = sdist[t];       int bi = t;
            float v2 = sdist[t + 32];
            if (v2 > bv) { bv = v2; bi = t + 32; }
            #pragma unroll
            for (int off = 16; off > 0; off >>= 1) {
                float ov = __shfl_down_sync(0xffffffffu, bv, off);
                int   oi = __shfl_down_sync(0xffffffffu, bi, off);
                if (ov > bv || (ov == bv && oi < bi)) { bv = ov; bi = oi; }
            }
            if (t == 0) s_far = bi;
        }
        __syncthreads();
    }

    if (t < 32) g_fps_idx[b * 32 + t] = sidx[t];
    for (int v = t; v < 32 * 32; v += 64) {
        int i = v >> 5, c = v & 31;
        out_coor[(b * 32 + i) * 32 + c] = coor[sidx[i]][c];
    }
}

// ---------------------------------------------------------------------------
// sparse_out[b,e,s] = sparse_fea[b,e,idx[b,s]]
// ---------------------------------------------------------------------------
__global__ void gather_sparse(const float* __restrict__ sp,
                              float* __restrict__ out)
{
    int t = blockIdx.x * 256 + threadIdx.x;     // < 524288
    int b = t >> 13;
    int r = t & 8191;
    int e = r >> 5;
    int s = r & 31;
    out[t] = sp[(size_t)(b * 256 + e) * 64 + g_fps_idx[b * 32 + s]];
}

// ---------------------------------------------------------------------------
// tf32 conv-as-GEMM, mainloop = pure LDS + MMA (no cvt, conflict-free banks).
// Block 256 thr, tile M=128 co x N=256 (8 strokes x 32 q), K=384 in 16x24.
// smem (float offsets):
//   ws0 0, ws1 3584            : tf32 weights [co128][28-stride, 24 used]
//   xe0 7168, xo0 9409         : x even/odd pos arrays [cl8][s8], strides
//   xe1 11652, xo1 13893         cl=280 (=24 mod 32), s=34  -> bank-perm
//   epilogue reuses smem as ys[64][268]
// Bank proof: B lanes (g,tig): bank = 24*tig + g + const  (bijective).
//             A lanes: bank = 28*g + tig + const          (bijective).
// ---------------------------------------------------------------------------
#define XE0 7168
#define XO0 9409
#define XE1 11652
#define XO1 13893

__global__ void __launch_bounds__(256, 1)
conv_mma_kernel(const float* __restrict__ dense)
{
    extern __shared__ float smem[];
    uint32_t* smem_u = (uint32_t*)smem;

    const int b    = blockIdx.y;
    const int ch   = blockIdx.x & 1;       // co half
    const int sgrp = blockIdx.x >> 1;      // 0..3
    const int co0  = ch * 128;
    const int t    = threadIdx.x;
    const int wp   = t >> 5;
    const int lane = t & 31;
    const int g    = lane >> 2;
    const int tig  = lane & 3;
    const int wm   = wp & 1;
    const int wn   = wp >> 1;
    const int m_warp = wm * 64;
    const int n_warp = wn * 64;

    __shared__ int stk[8];
    if (t < 8) stk[t] = g_fps_idx[b * 32 + sgrp * 8 + t];
    if (t < 128) {                         // zero xo col0 pads, both buffers
        int bi = t >> 6, r = t & 63;
        int cl = r >> 3, s = r & 7;
        smem[(bi ? XO1 : XO0) + 280 * cl + 34 * s] = 0.f;
    }
    __syncthreads();

    // staging helpers ------------------------------------------------------
    const int sv_row = t >> 4;             // 0..15 -> (cl, s) for x stage? no:
    // x stage: 64 rows(cl*8+s) x 16 float4; per thread 4 units.
    // weights: 768 float4 units; per thread 3.

    float4 xr[4];                          // LDG staging regs

    #define LDG_X(cc)                                                        \
        _Pragma("unroll")                                                    \
        for (int i = 0; i < 4; i++) {                                        \
            int v = t + 256 * i;                                             \
            int row = v >> 4, j = v & 15;                                    \
            int cl = row >> 3, s = row & 7;                                  \
            xr[i] = *(const float4*)&dense[(size_t)(b * 128 + (cc) * 8 + cl) \
                                           * 4096 + (size_t)stk[s] * 64 + j * 4]; \
        }

    #define STS_X(buf)                                                      \
        _Pragma("unroll")                                                    \
        for (int i = 0; i < 4; i++) {                                        \
            int v = t + 256 * i;                                             \
            int row = v >> 4, j = v & 15;                                    \
            int cl = row >> 3, s = row & 7;                                  \
            int base = 280 * cl + 34 * s + 2 * j;                            \
            uint32_t e0 = f2tf32(xr[i].x), e1 = f2tf32(xr[i].z);             \
            uint32_t o0 = f2tf32(xr[i].y), o1 = f2tf32(xr[i].w);             \
            *(uint2*)&smem_u[((buf) ? XE1 : XE0) + base] = make_uint2(e0, e1); \
            *(uint2*)&smem_u[((buf) ? XO1 : XO0) + base + 1] = make_uint2(o0, o1); \
        }

    #define STAGE_W(cc, buf)                                                \
        _Pragma("unroll")                                                    \
        for (int i = 0; i < 3; i++) {                                        \
            int v = t + 256 * i;                                             \
            int co = v / 6, seg = v - co * 6;                                \
            cp_async16(smem_addr(smem_u + (buf) * 3584 + co * 28 + seg * 4), \
                       g_wt + (size_t)(co0 + co) * 384 + (cc) * 24 + seg * 4); \
        }

    // prologue: chunk 0
    LDG_X(0);
    STAGE_W(0, 0);
    asm volatile("cp.async.commit_group;");
    asm volatile("cp.async.wait_group 0;");
    STS_X(0);
    __syncthreads();

    // fragment addressing
    const int abase = (m_warp + g) * 28 + tig;
    int off_n[8];
    #pragma unroll
    for (int nf = 0; nf < 8; nf++) {
        int n = n_warp + nf * 8 + g;
        off_n[nf] = 34 * (n >> 5) + (n & 31);
    }

    float acc[4][8][4];
    #pragma unroll
    for (int mf = 0; mf < 4; mf++)
        #pragma unroll
        for (int nf = 0; nf < 8; nf++)
            #pragma unroll
            for (int i = 0; i < 4; i++) acc[mf][nf][i] = 0.f;

    for (int c = 0; c < 16; ++c) {
        int pb = c & 1;
        if (c + 1 < 16) {
            LDG_X(c + 1);
            STAGE_W(c + 1, pb ^ 1);
        }
        asm volatile("cp.async.commit_group;");

        const uint32_t* wsb = smem_u + (pb ? 3584 : 0);
        const uint32_t* xeb = smem_u + (pb ? XE1 : XE0);
        const uint32_t* xob = smem_u + (pb ? XO1 : XO0);

        #pragma unroll
        for (int ks = 0; ks < 3; ks++) {
            const uint32_t* xp = (ks == 1) ? xeb : xob;
            const int cadd = (ks == 2) ? 1 : 0;
            uint32_t A[4][4];
            #pragma unroll
            for (int mf = 0; mf < 4; mf++) {
                int ai = abase + mf * 448 + ks * 8;
                A[mf][0] = wsb[ai];          // (g,   k)
                A[mf][1] = wsb[ai + 224];    // (g+8, k)
                A[mf][2] = wsb[ai + 4];      // (g,   k+4)
                A[mf][3] = wsb[ai + 228];    // (g+8, k+4)
            }
            #pragma unroll
            for (int nf = 0; nf < 8; nf++) {
                uint32_t B0 = xp[280 * tig + off_n[nf] + cadd];
                uint32_t B1 = xp[280 * tig + 1120 + off_n[nf] + cadd];
                #pragma unroll
                for (int mf = 0; mf < 4; mf++)
                    mma_tf32(acc[mf][nf], A[mf], B0, B1);
            }
        }
        asm volatile("cp.async.wait_group 0;");
        __syncthreads();
        if (c + 1 < 16) {
            STS_X(pb ^ 1);
            __syncthreads();
        }
    }

    // --- fused BN partial sums
    #pragma unroll
    for (int mf = 0; mf < 4; mf++) {
        float s0 = 0.f, q0 = 0.f, s1 = 0.f, q1 = 0.f;
        #pragma unroll
        for (int nf = 0; nf < 8; nf++) {
            float c0 = acc[mf][nf][0], c1 = acc[mf][nf][1];
            float c2 = acc[mf][nf][2], c3 = acc[mf][nf][3];
            s0 += c0 + c1;  q0 += c0 * c0 + c1 * c1;
            s1 += c2 + c3;  q1 += c2 * c2 + c3 * c3;
        }
        #pragma unroll
        for (int off = 1; off < 4; off <<= 1) {
            s0 += __shfl_xor_sync(0xffffffffu, s0, off);
            q0 += __shfl_xor_sync(0xffffffffu, q0, off);
            s1 += __shfl_xor_sync(0xffffffffu, s1, off);
            q1 += __shfl_xor_sync(0xffffffffu, q1, off);
        }
        if (tig == 0) {
            int co = co0 + m_warp + mf * 16 + g;
            atomicAdd(&g_sum[co],       s0);
            atomicAdd(&g_sqsum[co],     q0);
            atomicAdd(&g_sum[co + 8],   s1);
            atomicAdd(&g_sqsum[co + 8], q1);
        }
    }

    // --- epilogue: two-phase smem transpose, coalesced STG
    float* ys = smem;                      // [64][268]
    #pragma unroll
    for (int ph = 0; ph < 2; ph++) {
        __syncthreads();
        if (wm == ph) {
            #pragma unroll
            for (int mf = 0; mf < 4; mf++)
                #pragma unroll
                for (int nf = 0; nf < 8; nf++) {
                    int row = mf * 16 + g;
                    int nC  = n_warp + nf * 8 + 2 * tig;
                    *(float2*)&ys[row * 268 + nC] =
                        make_float2(acc[mf][nf][0], acc[mf][nf][1]);
                    *(float2*)&ys[(row + 8) * 268 + nC] =
                        make_float2(acc[mf][nf][2], acc[mf][nf][3]);
                }
        }
        __syncthreads();
        int row = t >> 2, jb = t & 3;
        float* dst = g_y + ((size_t)(b * 256 + co0 + ph * 64 + row)) * 1024 +
                     sgrp * 256;
        #pragma unroll
        for (int jj = 0; jj < 16; jj++) {
            int j = jb + jj * 4;
            *(float4*)(dst + j * 4) = *(const float4*)&ys[row * 268 + j * 4];
        }
    }
}

// ---------------------------------------------------------------------------
// Normalize + scale/shift + tanh-GELU; stats finalized inline per thread.
// ---------------------------------------------------------------------------
__global__ void bn_gelu_kernel(const float* __restrict__ gamma,
                               const float* __restrict__ beta,
                               float* __restrict__ out)
{
    int i4 = blockIdx.x * 256 + threadIdx.x;   // < 4194304
    int co = (i4 >> 8) & 255;
    float mean = g_sum[co] * (1.f / 65536.f);
    float var  = g_sqsum[co] * (1.f / 65536.f) - mean * mean;
    float ga = rsqrtf(var + 1e-5f) * gamma[co];
    float be = beta[co];
    float4 v = *(const float4*)&g_y[(size_t)i4 * 4];
    float4 r;
    {
        float x = (v.x - mean) * ga + be;
        float u = 0.7978845608028654f * (x + 0.044715f * x * x * x);
        r.x = 0.5f * x * (1.f + tanhf(u));
    }
    {
        float x = (v.y - mean) * ga + be;
        float u = 0.7978845608028654f * (x + 0.044715f * x * x * x);
        r.y = 0.5f * x * (1.f + tanhf(u));
    }
    {
        float x = (v.z - mean) * ga + be;
        float u = 0.7978845608028654f * (x + 0.044715f * x * x * x);
        r.z = 0.5f * x * (1.f + tanhf(u));
    }
    {
        float x = (v.w - mean) * ga + be;
        float u = 0.7978845608028654f * (x + 0.044715f * x * x * x);
        r.w = 0.5f * x * (1.f + tanhf(u));
    }
    *(float4*)&out[(size_t)i4 * 4] = r;
}

// ---------------------------------------------------------------------------
extern "C" void kernel_launch(void* const* d_in, const int* in_sizes, int n_in,
                              void* d_out, int out_size)
{
    const float* sparse_fea = (const float*)d_in[0];
    const float* dense_fea  = (const float*)d_in[1];
    const float* stk_coor   = (const float*)d_in[2];
    const float* conv_w     = (const float*)d_in[3];
    // d_in[4] = conv_b: zeros AND cancels under batch-stat BN.
    const float* bn_gamma   = (const float*)d_in[5];
    const float* bn_beta    = (const float*)d_in[6];
    float* out = (float*)d_out;

    cudaFuncSetAttribute(conv_mma_kernel,
                         cudaFuncAttributeMaxDynamicSharedMemorySize, 68608);

    wprep_kernel<<<256, 384>>>(conv_w);
    fps_kernel<<<64, 64>>>(stk_coor, out + OFF_COOR);
    gather_sparse<<<2048, 256>>>(sparse_fea, out);
    conv_mma_kernel<<<dim3(8, 64), 256, 68608>>>(dense_fea);
    bn_gelu_kernel<<<16384, 256>>>(bn_gamma, bn_beta, out + OFF_DENSE);
}

// round 4
// speedup vs baseline: 3.6312x; 1.0045x over previous
#include <cuda_runtime.h>
#include <math.h>
#include <stdint.h>

// ---------------------------------------------------------------------------
// Shapes: sparse_fea[64,256,64] dense_fea[64,128,4096] stk_coor[64,64,32]
//         conv_w[256,128,3] (flat [256][384]) bn_gamma/beta[256]
// Output: sparse_out[64,256,32] | dense_out[64,256,1024] | coor[64,32,32]
// ---------------------------------------------------------------------------

#define OFF_DENSE 524288
#define OFF_COOR  (524288 + 16777216)

__device__ int      g_fps_idx[64 * 32];
__device__ float    g_y[64 * 256 * 1024];     // conv output scratch
__device__ float    g_sum[256];
__device__ float    g_sqsum[256];
__device__ uint32_t g_wt[256 * 384];          // tf32 weights, tap-major per chunk

__device__ __forceinline__ unsigned smem_addr(const void* p) {
    return (unsigned)__cvta_generic_to_shared(p);
}
__device__ __forceinline__ void cp_async16(unsigned dst, const void* src) {
    asm volatile("cp.async.cg.shared.global [%0], [%1], 16;\n" :: "r"(dst), "l"(src));
}
__device__ __forceinline__ uint32_t f2tf32(float f) {
    uint32_t u;
    asm("cvt.rna.tf32.f32 %0, %1;" : "=r"(u) : "f"(f));
    return u;
}
__device__ __forceinline__ float tanh_fast(float x) {
    float r;
    asm("tanh.approx.f32 %0, %1;" : "=f"(r) : "f"(x));
    return r;
}
__device__ __forceinline__ void mma_tf32(float c[4], const uint32_t a[4],
                                         uint32_t b0, uint32_t b1) {
    asm volatile(
        "mma.sync.aligned.m16n8k8.row.col.f32.tf32.tf32.f32 "
        "{%0,%1,%2,%3},{%4,%5,%6,%7},{%8,%9},{%0,%1,%2,%3};"
        : "+f"(c[0]), "+f"(c[1]), "+f"(c[2]), "+f"(c[3])
        : "r"(a[0]), "r"(a[1]), "r"(a[2]), "r"(a[3]), "r"(b0), "r"(b1));
}

// ---------------------------------------------------------------------------
// Weight prep: reorder to [co][chunk16][tap3][cl8], pre-convert to tf32.
// ---------------------------------------------------------------------------
__global__ void wprep_kernel(const float* __restrict__ w)
{
    int co = blockIdx.x;                 // 256
    int r  = threadIdx.x;                // 384
    int c   = r / 24;
    int q2  = r - c * 24;
    int tap = q2 >> 3;
    int cl  = q2 & 7;
    g_wt[co * 384 + r] = f2tf32(w[co * 384 + (c * 8 + cl) * 3 + tap]);
}

// ---------------------------------------------------------------------------
// FPS: one block per batch, 64 threads. Block 0 zeroes BN accumulators.
// ---------------------------------------------------------------------------
__global__ void fps_kernel(const float* __restrict__ stk_coor,
                           float* __restrict__ out_coor)
{
    int b = blockIdx.x;
    int t = threadIdx.x;                     // 0..63

    if (b == 0) {
        for (int i = t; i < 256; i += 64) { g_sum[i] = 0.f; g_sqsum[i] = 0.f; }
    }

    __shared__ float coor[64][33];
    __shared__ float sdist[64];
    __shared__ int   sidx[32];
    __shared__ int   s_far;

    #pragma unroll
    for (int c = 0; c < 32; c++)
        coor[t][c] = stk_coor[(b * 64 + t) * 32 + c];
    if (t == 0) s_far = 0;
    float dist = 1e10f;
    __syncthreads();

    for (int i = 0; i < 32; i++) {
        int far = s_far;
        if (t == 0) sidx[i] = far;
        float d = 0.f;
        #pragma unroll
        for (int c = 0; c < 32; c++) {
            float df = coor[t][c] - coor[far][c];
            d += df * df;
        }
        dist = fminf(dist, d);
        sdist[t] = dist;
        __syncthreads();
        if (t < 32) {
            float bv = sdist[t];       int bi = t;
            float v2 = sdist[t + 32];
            if (v2 > bv) { bv = v2; bi = t + 32; }
            #pragma unroll
            for (int off = 16; off > 0; off >>= 1) {
                float ov = __shfl_down_sync(0xffffffffu, bv, off);
                int   oi = __shfl_down_sync(0xffffffffu, bi, off);
                if (ov > bv || (ov == bv && oi < bi)) { bv = ov; bi = oi; }
            }
            if (t == 0) s_far = bi;
        }
        __syncthreads();
    }

    if (t < 32) g_fps_idx[b * 32 + t] = sidx[t];
    for (int v = t; v < 32 * 32; v += 64) {
        int i = v >> 5, c = v & 31;
        out_coor[(b * 32 + i) * 32 + c] = coor[sidx[i]][c];
    }
}

// ---------------------------------------------------------------------------
// sparse_out[b,e,s] = sparse_fea[b,e,idx[b,s]]
// ---------------------------------------------------------------------------
__global__ void gather_sparse(const float* __restrict__ sp,
                              float* __restrict__ out)
{
    int t = blockIdx.x * 256 + threadIdx.x;     // < 524288
    int b = t >> 13;
    int r = t & 8191;
    int e = r >> 5;
    int s = r & 31;
    out[t] = sp[(size_t)(b * 256 + e) * 64 + g_fps_idx[b * 32 + s]];
}

// ---------------------------------------------------------------------------
// tf32 conv-as-GEMM. 512 threads (16 warps), tile M=128 x N=256, K=384 in
// 16 chunks of 24 (8 cin x 3 taps). Warp tile 32x64 (acc 2x8x4).
// smem (float offsets):
//   ws0 0, ws1 3584            : tf32 weights [co128][28-stride, 24 used]
//   xe0 7168, xo0 9409         : x even/odd pos arrays, strides cl=280, s=34
//   xe1 11652, xo1 13893         (bank-permutation proven conflict-free)
//   epilogue reuses smem as ys[64][268]
// ---------------------------------------------------------------------------
#define XE0 7168
#define XO0 9409
#define XE1 11652
#define XO1 13893

__global__ void __launch_bounds__(512, 1)
conv_mma_kernel(const float* __restrict__ dense)
{
    extern __shared__ float smem[];
    uint32_t* smem_u = (uint32_t*)smem;

    const int b    = blockIdx.y;
    const int ch   = blockIdx.x & 1;       // co half
    const int sgrp = blockIdx.x >> 1;      // 0..3
    const int co0  = ch * 128;
    const int t    = threadIdx.x;
    const int wp   = t >> 5;               // 0..15
    const int lane = t & 31;
    const int g    = lane >> 2;
    const int tig  = lane & 3;
    const int wm   = wp & 3;               // 0..3 -> m_warp 32*wm
    const int wn   = wp >> 2;              // 0..3 -> n_warp 64*wn
    const int m_warp = wm * 32;
    const int n_warp = wn * 64;

    __shared__ int stk[8];
    if (t < 8) stk[t] = g_fps_idx[b * 32 + sgrp * 8 + t];
    if (t < 128) {                         // zero xo col0 pads, both buffers
        int bi = t >> 6, r = t & 63;
        int cl = r >> 3, s = r & 7;
        smem[(bi ? XO1 : XO0) + 280 * cl + 34 * s] = 0.f;
    }
    __syncthreads();

    float4 xr[2];                          // LDG staging regs

    #define LDG_X(cc)                                                        \
        _Pragma("unroll")                                                    \
        for (int i = 0; i < 2; i++) {                                        \
            int v = t + 512 * i;                                             \
            int row = v >> 4, j = v & 15;                                    \
            int cl = row >> 3, s = row & 7;                                  \
            xr[i] = *(const float4*)&dense[(size_t)(b * 128 + (cc) * 8 + cl) \
                                           * 4096 + (size_t)stk[s] * 64 + j * 4]; \
        }

    #define STS_X(buf)                                                      \
        _Pragma("unroll")                                                    \
        for (int i = 0; i < 2; i++) {                                        \
            int v = t + 512 * i;                                             \
            int row = v >> 4, j = v & 15;                                    \
            int cl = row >> 3, s = row & 7;                                  \
            int base = 280 * cl + 34 * s + 2 * j;                            \
            uint32_t e0 = f2tf32(xr[i].x), e1 = f2tf32(xr[i].z);             \
            uint32_t o0 = f2tf32(xr[i].y), o1 = f2tf32(xr[i].w);             \
            *(uint2*)&smem_u[((buf) ? XE1 : XE0) + base] = make_uint2(e0, e1); \
            *(uint2*)&smem_u[((buf) ? XO1 : XO0) + base + 1] = make_uint2(o0, o1); \
        }

    #define STAGE_W(cc, buf)                                                \
        for (int v = t; v < 768; v += 512) {                                 \
            int co = v / 6, seg = v - co * 6;                                \
            cp_async16(smem_addr(smem_u + (buf) * 3584 + co * 28 + seg * 4), \
                       g_wt + (size_t)(co0 + co) * 384 + (cc) * 24 + seg * 4); \
        }

    // prologue: chunk 0
    LDG_X(0);
    STAGE_W(0, 0);
    asm volatile("cp.async.commit_group;");
    asm volatile("cp.async.wait_group 0;");
    STS_X(0);
    __syncthreads();

    // fragment addressing
    const int abase = (m_warp + g) * 28 + tig;
    int off_n[8];
    #pragma unroll
    for (int nf = 0; nf < 8; nf++) {
        int n = n_warp + nf * 8 + g;
        off_n[nf] = 34 * (n >> 5) + (n & 31);
    }

    float acc[2][8][4];
    #pragma unroll
    for (int mf = 0; mf < 2; mf++)
        #pragma unroll
        for (int nf = 0; nf < 8; nf++)
            #pragma unroll
            for (int i = 0; i < 4; i++) acc[mf][nf][i] = 0.f;

    for (int c = 0; c < 16; ++c) {
        int pb = c & 1;
        if (c + 1 < 16) {
            LDG_X(c + 1);
            STAGE_W(c + 1, pb ^ 1);
        }
        asm volatile("cp.async.commit_group;");

        const uint32_t* wsb = smem_u + (pb ? 3584 : 0);
        const uint32_t* xeb = smem_u + (pb ? XE1 : XE0);
        const uint32_t* xob = smem_u + (pb ? XO1 : XO0);

        #pragma unroll
        for (int ks = 0; ks < 3; ks++) {
            const uint32_t* xp = (ks == 1) ? xeb : xob;
            const int cadd = (ks == 2) ? 1 : 0;
            uint32_t A[2][4];
            #pragma unroll
            for (int mf = 0; mf < 2; mf++) {
                int ai = abase + mf * 448 + ks * 8;
                A[mf][0] = wsb[ai];          // (g,   k)
                A[mf][1] = wsb[ai + 224];    // (g+8, k)
                A[mf][2] = wsb[ai + 4];      // (g,   k+4)
                A[mf][3] = wsb[ai + 228];    // (g+8, k+4)
            }
            #pragma unroll
            for (int nf = 0; nf < 8; nf++) {
                uint32_t B0 = xp[280 * tig + off_n[nf] + cadd];
                uint32_t B1 = xp[280 * tig + 1120 + off_n[nf] + cadd];
                #pragma unroll
                for (int mf = 0; mf < 2; mf++)
                    mma_tf32(acc[mf][nf], A[mf], B0, B1);
            }
        }
        asm volatile("cp.async.wait_group 0;");
        __syncthreads();
        if (c + 1 < 16) {
            STS_X(pb ^ 1);
            __syncthreads();
        }
    }

    // --- fused BN partial sums
    #pragma unroll
    for (int mf = 0; mf < 2; mf++) {
        float s0 = 0.f, q0 = 0.f, s1 = 0.f, q1 = 0.f;
        #pragma unroll
        for (int nf = 0; nf < 8; nf++) {
            float c0 = acc[mf][nf][0], c1 = acc[mf][nf][1];
            float c2 = acc[mf][nf][2], c3 = acc[mf][nf][3];
            s0 += c0 + c1;  q0 += c0 * c0 + c1 * c1;
            s1 += c2 + c3;  q1 += c2 * c2 + c3 * c3;
        }
        #pragma unroll
        for (int off = 1; off < 4; off <<= 1) {
            s0 += __shfl_xor_sync(0xffffffffu, s0, off);
            q0 += __shfl_xor_sync(0xffffffffu, q0, off);
            s1 += __shfl_xor_sync(0xffffffffu, s1, off);
            q1 += __shfl_xor_sync(0xffffffffu, q1, off);
        }
        if (tig == 0) {
            int co = co0 + m_warp + mf * 16 + g;
            atomicAdd(&g_sum[co],       s0);
            atomicAdd(&g_sqsum[co],     q0);
            atomicAdd(&g_sum[co + 8],   s1);
            atomicAdd(&g_sqsum[co + 8], q1);
        }
    }

    // --- epilogue: two-phase smem transpose (64 co rows each), coalesced STG
    float* ys = smem;                      // [64][268]
    #pragma unroll
    for (int ph = 0; ph < 2; ph++) {
        __syncthreads();
        if ((wm >> 1) == ph) {
            #pragma unroll
            for (int mf = 0; mf < 2; mf++)
                #pragma unroll
                for (int nf = 0; nf < 8; nf++) {
                    int row = (wm & 1) * 32 + mf * 16 + g;
                    int nC  = n_warp + nf * 8 + 2 * tig;
                    *(float2*)&ys[row * 268 + nC] =
                        make_float2(acc[mf][nf][0], acc[mf][nf][1]);
                    *(float2*)&ys[(row + 8) * 268 + nC] =
                        make_float2(acc[mf][nf][2], acc[mf][nf][3]);
                }
        }
        __syncthreads();
        int row = t >> 3, jb = t & 7;
        float* dst = g_y + ((size_t)(b * 256 + co0 + ph * 64 + row)) * 1024 +
                     sgrp * 256;
        #pragma unroll
        for (int jj = 0; jj < 8; jj++) {
            int j = jb + jj * 8;
            *(float4*)(dst + j * 4) = *(const float4*)&ys[row * 268 + j * 4];
        }
    }
}

// ---------------------------------------------------------------------------
// Normalize + scale/shift + tanh-GELU (tanh.approx); stats finalized inline.
// ---------------------------------------------------------------------------
__global__ void bn_gelu_kernel(const float* __restrict__ gamma,
                               const float* __restrict__ beta,
                               float* __restrict__ out)
{
    int i4 = blockIdx.x * 256 + threadIdx.x;   // < 4194304
    int co = (i4 >> 8) & 255;
    float mean = g_sum[co] * (1.f / 65536.f);
    float var  = g_sqsum[co] * (1.f / 65536.f) - mean * mean;
    float ga = rsqrtf(var + 1e-5f) * gamma[co];
    float be = beta[co];
    float4 v = *(const float4*)&g_y[(size_t)i4 * 4];
    float4 r;
    {
        float x = (v.x - mean) * ga + be;
        float u = 0.7978845608028654f * (x + 0.044715f * x * x * x);
        r.x = 0.5f * x * (1.f + tanh_fast(u));
    }
    {
        float x = (v.y - mean) * ga + be;
        float u = 0.7978845608028654f * (x + 0.044715f * x * x * x);
        r.y = 0.5f * x * (1.f + tanh_fast(u));
    }
    {
        float x = (v.z - mean) * ga + be;
        float u = 0.7978845608028654f * (x + 0.044715f * x * x * x);
        r.z = 0.5f * x * (1.f + tanh_fast(u));
    }
    {
        float x = (v.w - mean) * ga + be;
        float u = 0.7978845608028654f * (x + 0.044715f * x * x * x);
        r.w = 0.5f * x * (1.f + tanh_fast(u));
    }
    *(float4*)&out[(size_t)i4 * 4] = r;
}

// ---------------------------------------------------------------------------
extern "C" void kernel_launch(void* const* d_in, const int* in_sizes, int n_in,
                              void* d_out, int out_size)
{
    const float* sparse_fea = (const float*)d_in[0];
    const float* dense_fea  = (const float*)d_in[1];
    const float* stk_coor   = (const float*)d_in[2];
    const float* conv_w     = (const float*)d_in[3];
    // d_in[4] = conv_b: zeros AND cancels under batch-stat BN.
    const float* bn_gamma   = (const float*)d_in[5];
    const float* bn_beta    = (const float*)d_in[6];
    float* out = (float*)d_out;

    cudaFuncSetAttribute(conv_mma_kernel,
                         cudaFuncAttributeMaxDynamicSharedMemorySize, 68608);

    wprep_kernel<<<256, 384>>>(conv_w);
    fps_kernel<<<64, 64>>>(stk_coor, out + OFF_COOR);
    gather_sparse<<<2048, 256>>>(sparse_fea, out);
    conv_mma_kernel<<<dim3(8, 64), 512, 68608>>>(dense_fea);
    bn_gelu_kernel<<<16384, 256>>>(bn_gamma, bn_beta, out + OFF_DENSE);
}

// round 6
// speedup vs baseline: 3.9672x; 1.0925x over previous
#include <cuda_runtime.h>
#include <cuda_fp16.h>
#include <math.h>
#include <stdint.h>

// ---------------------------------------------------------------------------
// Shapes: sparse_fea[64,256,64] dense_fea[64,128,4096] stk_coor[64,64,32]
//         conv_w[256,128,3] (flat [256][384]) bn_gamma/beta[256]
// Output: sparse_out[64,256,32] | dense_out[64,256,1024] | coor[64,32,32]
// ---------------------------------------------------------------------------

#define OFF_DENSE 524288
#define OFF_COOR  (524288 + 16777216)

__device__ int      g_fps_idx[64 * 32];
__device__ float    g_y[64 * 256 * 1024];     // conv output scratch
__device__ float    g_sum[256];
__device__ float    g_sqsum[256];
__device__ uint32_t g_wth[256 * 192];         // fp16 weights [co][chunk16][12 half2]

__device__ __forceinline__ unsigned smem_addr(const void* p) {
    return (unsigned)__cvta_generic_to_shared(p);
}
__device__ __forceinline__ void cp_async16(unsigned dst, const void* src) {
    asm volatile("cp.async.cg.shared.global [%0], [%1], 16;\n" :: "r"(dst), "l"(src));
}
__device__ __forceinline__ float tanh_fast(float x) {
    float r;
    asm("tanh.approx.f32 %0, %1;" : "=f"(r) : "f"(x));
    return r;
}
__device__ __forceinline__ void mma16(float c[4], const uint32_t a[4],
                                      uint32_t b0, uint32_t b1) {
    asm volatile(
        "mma.sync.aligned.m16n8k16.row.col.f32.f16.f16.f32 "
        "{%0,%1,%2,%3},{%4,%5,%6,%7},{%8,%9},{%0,%1,%2,%3};"
        : "+f"(c[0]), "+f"(c[1]), "+f"(c[2]), "+f"(c[3])
        : "r"(a[0]), "r"(a[1]), "r"(a[2]), "r"(a[3]), "r"(b0), "r"(b1));
}
__device__ __forceinline__ void mma8(float c[4], uint32_t a0, uint32_t a1,
                                     uint32_t b0) {
    asm volatile(
        "mma.sync.aligned.m16n8k8.row.col.f32.f16.f16.f32 "
        "{%0,%1,%2,%3},{%4,%5},{%6},{%0,%1,%2,%3};"
        : "+f"(c[0]), "+f"(c[1]), "+f"(c[2]), "+f"(c[3])
        : "r"(a0), "r"(a1), "r"(b0));
}
__device__ __forceinline__ uint32_t pack_h2(float lo, float hi) {
    __half2 h = __floats2half2_rn(lo, hi);      // .x = lo (low 16 bits)
    return *(uint32_t*)&h;
}

// ---------------------------------------------------------------------------
// Weight prep: fp16, ordering [co][chunk c][k24], k = cl_local*3 + tap,
// packed as 12 half2 words per (co, chunk).
// ---------------------------------------------------------------------------
__global__ void wprep_kernel(const float* __restrict__ w)
{
    int co = blockIdx.x;                 // 256
    int t  = threadIdx.x;                // 0..191
    int c  = t / 12;
    int j  = t - c * 12;                 // half2 index
    int k0 = 2 * j, k1 = 2 * j + 1;
    int cin0 = c * 8 + k0 / 3, tap0 = k0 % 3;
    int cin1 = c * 8 + k1 / 3, tap1 = k1 % 3;
    float f0 = w[co * 384 + cin0 * 3 + tap0];
    float f1 = w[co * 384 + cin1 * 3 + tap1];
    g_wth[co * 192 + c * 12 + j] = pack_h2(f0, f1);
}

// ---------------------------------------------------------------------------
// FPS: one block per batch, 64 threads. Block 0 zeroes BN accumulators.
// ---------------------------------------------------------------------------
__global__ void fps_kernel(const float* __restrict__ stk_coor,
                           float* __restrict__ out_coor)
{
    int b = blockIdx.x;
    int t = threadIdx.x;                     // 0..63

    if (b == 0) {
        for (int i = t; i < 256; i += 64) { g_sum[i] = 0.f; g_sqsum[i] = 0.f; }
    }

    __shared__ float coor[64][33];
    __shared__ float sdist[64];
    __shared__ int   sidx[32];
    __shared__ int   s_far;

    #pragma unroll
    for (int c = 0; c < 32; c++)
        coor[t][c] = stk_coor[(b * 64 + t) * 32 + c];
    if (t == 0) s_far = 0;
    float dist = 1e10f;
    __syncthreads();

    for (int i = 0; i < 32; i++) {
        int far = s_far;
        if (t == 0) sidx[i] = far;
        float d = 0.f;
        #pragma unroll
        for (int c = 0; c < 32; c++) {
            float df = coor[t][c] - coor[far][c];
            d += df * df;
        }
        dist = fminf(dist, d);
        sdist[t] = dist;
        __syncthreads();
        if (t < 32) {
            float bv = sdist[t];       int bi = t;
            float v2 = sdist[t + 32];
            if (v2 > bv) { bv = v2; bi = t + 32; }
            #pragma unroll
            for (int off = 16; off > 0; off >>= 1) {
                float ov = __shfl_down_sync(0xffffffffu, bv, off);
                int   oi = __shfl_down_sync(0xffffffffu, bi, off);
                if (ov > bv || (ov == bv && oi < bi)) { bv = ov; bi = oi; }
            }
            if (t == 0) s_far = bi;
        }
        __syncthreads();
    }

    if (t < 32) g_fps_idx[b * 32 + t] = sidx[t];
    for (int v = t; v < 32 * 32; v += 64) {
        int i = v >> 5, c = v & 31;
        out_coor[(b * 32 + i) * 32 + c] = coor[sidx[i]][c];
    }
}

// ---------------------------------------------------------------------------
// sparse_out[b,e,s] = sparse_fea[b,e,idx[b,s]]
// ---------------------------------------------------------------------------
__global__ void gather_sparse(const float* __restrict__ sp,
                              float* __restrict__ out)
{
    int t = blockIdx.x * 256 + threadIdx.x;     // < 524288
    int b = t >> 13;
    int r = t & 8191;
    int e = r >> 5;
    int s = r & 31;
    out[t] = sp[(size_t)(b * 256 + e) * 64 + g_fps_idx[b * 32 + s]];
}

// ---------------------------------------------------------------------------
// fp16 conv-as-GEMM. 512 threads, tile M=128 co x N=256 (8 strokes x 32 q),
// K=384 in 16 chunks of 24 (8 cin x 3 taps), mma = m16n8k16 + m16n8k8.
// smem layout (32-bit word offsets):
//   WB0 0      : fp16 weights [128 co][20 words, 12 used] (double buf @2560)
//   BB  5120   : im2col B [256 n][20 words, 12 used]  (single buffer)
//   RAW 10240  : raw x rows [cl8*s8][72], x[p] at word p+4, zero at word 3
// Bank perms: A/B fragment lanes hit bank (20g+tig)%32 -> bijective.
// Epilogue reuses smem as ys[64][268].
// ---------------------------------------------------------------------------
#define WB1 2560
#define BB  5120
#define RAW 10240

__global__ void __launch_bounds__(512, 1)
conv_mma_kernel(const float* __restrict__ dense)
{
    extern __shared__ float smem[];
    uint32_t* smem_u = (uint32_t*)smem;

    const int b    = blockIdx.y;
    const int ch   = blockIdx.x & 1;       // co half
    const int sgrp = blockIdx.x >> 1;      // 0..3
    const int co0  = ch * 128;
    const int t    = threadIdx.x;
    const int wp   = t >> 5;               // 0..15
    const int lane = t & 31;
    const int g    = lane >> 2;
    const int tig  = lane & 3;
    const int wm   = wp & 3;
    const int wn   = wp >> 2;
    const int m_warp = wm * 32;
    const int n_warp = wn * 64;

    __shared__ int stk[8];
    if (t < 8) stk[t] = g_fps_idx[b * 32 + sgrp * 8 + t];
    if (t < 64) smem[RAW + t * 72 + 3] = 0.f;   // p = -1 zero pad per raw row
    __syncthreads();                       // stk + pads visible BEFORE any use

    float4 xr[2];

    #define LDG_X(cc)                                                        \
        _Pragma("unroll")                                                    \
        for (int i = 0; i < 2; i++) {                                        \
            int v = t + 512 * i;                                             \
            int row = v >> 4, j = v & 15;                                    \
            int cl = row >> 3, s = row & 7;                                  \
            xr[i] = *(const float4*)&dense[(size_t)(b * 128 + (cc) * 8 + cl) \
                                           * 4096 + (size_t)stk[s] * 64 + j * 4]; \
        }

    #define STS_RAW                                                          \
        _Pragma("unroll")                                                    \
        for (int i = 0; i < 2; i++) {                                        \
            int v = t + 512 * i;                                             \
            int row = v >> 4, j = v & 15;                                    \
            *(float4*)&smem[RAW + row * 72 + 4 + 4 * j] = xr[i];             \
        }

    #define STAGE_W(cc, buf)                                                 \
        if (t < 384) {                                                       \
            int co = t / 3, seg = t - co * 3;                                \
            cp_async16(smem_addr(smem_u + (buf) * WB1 + co * 20 + seg * 4),  \
                       g_wth + (size_t)(co0 + co) * 192 + (cc) * 12 + seg * 4); \
        }

    // im2col build: thread covers n = t&255, k-half h2 = t>>8 (6 half2 each)
    #define BUILD_B                                                          \
        {                                                                    \
            int n  = t & 255;                                                \
            int h2 = t >> 8;                                                 \
            int s  = n >> 5, q = n & 31;                                     \
            float f[12];                                                     \
            _Pragma("unroll")                                                \
            for (int cr = 0; cr < 4; cr++) {                                 \
                const float* rrow = smem + RAW + (h2 * 4 + cr) * 576 +       \
                                    s * 72 + 2 * q;                          \
                float2 u0 = *(const float2*)(rrow + 2);                      \
                float2 u1 = *(const float2*)(rrow + 4);                      \
                f[cr * 3 + 0] = u0.y;                                        \
                f[cr * 3 + 1] = u1.x;                                        \
                f[cr * 3 + 2] = u1.y;                                        \
            }                                                                \
            uint32_t* dst = smem_u + BB + n * 20 + h2 * 6;                   \
            ((uint2*)dst)[0] = make_uint2(pack_h2(f[0], f[1]),               \
                                          pack_h2(f[2], f[3]));              \
            ((uint2*)(dst + 2))[0] = make_uint2(pack_h2(f[4], f[5]),         \
                                                pack_h2(f[6], f[7]));        \
            ((uint2*)(dst + 4))[0] = make_uint2(pack_h2(f[8], f[9]),         \
                                                pack_h2(f[10], f[11]));      \
        }

    // prologue: chunk 0
    LDG_X(0);
    STAGE_W(0, 0);
    asm volatile("cp.async.commit_group;");
    STS_RAW;
    asm volatile("cp.async.wait_group 0;");
    __syncthreads();
    BUILD_B;
    __syncthreads();

    // fragment base offsets (word units)
    const int abase = m_warp * 20 + g * 20 + tig;          // + buf*WB1
    const int bbase = BB + (n_warp + g) * 20 + tig;        // + nf*160

    float acc[2][8][4];
    #pragma unroll
    for (int mf = 0; mf < 2; mf++)
        #pragma unroll
        for (int nf = 0; nf < 8; nf++)
            #pragma unroll
            for (int i = 0; i < 4; i++) acc[mf][nf][i] = 0.f;

    for (int c = 0; c < 16; ++c) {
        int pb = c & 1;
        if (c + 1 < 16) {
            LDG_X(c + 1);
            STAGE_W(c + 1, pb ^ 1);
        }
        asm volatile("cp.async.commit_group;");

        const uint32_t* aw = smem_u + pb * WB1 + abase;

        // k16 step (k_local 0..15)
        {
            uint32_t A[2][4];
            #pragma unroll
            for (int mf = 0; mf < 2; mf++) {
                A[mf][0] = aw[mf * 320];
                A[mf][1] = aw[mf * 320 + 160];
                A[mf][2] = aw[mf * 320 + 4];
                A[mf][3] = aw[mf * 320 + 164];
            }
            #pragma unroll
            for (int nf = 0; nf < 8; nf++) {
                uint32_t B0 = smem_u[bbase + nf * 160];
                uint32_t B1 = smem_u[bbase + nf * 160 + 4];
                mma16(acc[0][nf], A[0], B0, B1);
                mma16(acc[1][nf], A[1], B0, B1);
            }
        }
        // k8 step (k_local 16..23)
        {
            uint32_t A0a = aw[8],       A0b = aw[168];
            uint32_t A1a = aw[320 + 8], A1b = aw[320 + 168];
            #pragma unroll
            for (int nf = 0; nf < 8; nf++) {
                uint32_t B0 = smem_u[bbase + nf * 160 + 8];
                mma8(acc[0][nf], A0a, A0b, B0);
                mma8(acc[1][nf], A1a, A1b, B0);
            }
        }

        if (c + 1 < 16) STS_RAW;
        asm volatile("cp.async.wait_group 0;");
        __syncthreads();
        if (c + 1 < 16) {
            BUILD_B;
            __syncthreads();
        }
    }

    // --- fused BN partial sums
    #pragma unroll
    for (int mf = 0; mf < 2; mf++) {
        float s0 = 0.f, q0 = 0.f, s1 = 0.f, q1 = 0.f;
        #pragma unroll
        for (int nf = 0; nf < 8; nf++) {
            float c0 = acc[mf][nf][0], c1 = acc[mf][nf][1];
            float c2 = acc[mf][nf][2], c3 = acc[mf][nf][3];
            s0 += c0 + c1;  q0 += c0 * c0 + c1 * c1;
            s1 += c2 + c3;  q1 += c2 * c2 + c3 * c3;
        }
        #pragma unroll
        for (int off = 1; off < 4; off <<= 1) {
            s0 += __shfl_xor_sync(0xffffffffu, s0, off);
            q0 += __shfl_xor_sync(0xffffffffu, q0, off);
            s1 += __shfl_xor_sync(0xffffffffu, s1, off);
            q1 += __shfl_xor_sync(0xffffffffu, q1, off);
        }
        if (tig == 0) {
            int co = co0 + m_warp + mf * 16 + g;
            atomicAdd(&g_sum[co],       s0);
            atomicAdd(&g_sqsum[co],     q0);
            atomicAdd(&g_sum[co + 8],   s1);
            atomicAdd(&g_sqsum[co + 8], q1);
        }
    }

    // --- epilogue: two-phase smem transpose (64 co rows each), coalesced STG
    float* ys = smem;                      // [64][268]
    #pragma unroll
    for (int ph = 0; ph < 2; ph++) {
        __syncthreads();
        if ((wm >> 1) == ph) {
            #pragma unroll
            for (int mf = 0; mf < 2; mf++)
                #pragma unroll
                for (int nf = 0; nf < 8; nf++) {
                    int row = (wm & 1) * 32 + mf * 16 + g;
                    int nC  = n_warp + nf * 8 + 2 * tig;
                    *(float2*)&ys[row * 268 + nC] =
                        make_float2(acc[mf][nf][0], acc[mf][nf][1]);
                    *(float2*)&ys[(row + 8) * 268 + nC] =
                        make_float2(acc[mf][nf][2], acc[mf][nf][3]);
                }
        }
        __syncthreads();
        int row = t >> 3, jb = t & 7;
        float* dst = g_y + ((size_t)(b * 256 + co0 + ph * 64 + row)) * 1024 +
                     sgrp * 256;
        #pragma unroll
        for (int jj = 0; jj < 8; jj++) {
            int j = jb + jj * 8;
            *(float4*)(dst + j * 4) = *(const float4*)&ys[row * 268 + j * 4];
        }
    }
}

// ---------------------------------------------------------------------------
// Normalize + scale/shift + tanh-GELU (tanh.approx); stats finalized inline.
// ---------------------------------------------------------------------------
__global__ void bn_gelu_kernel(const float* __restrict__ gamma,
                               const float* __restrict__ beta,
                               float* __restrict__ out)
{
    int i4 = blockIdx.x * 256 + threadIdx.x;   // < 4194304
    int co = (i4 >> 8) & 255;
    float mean = g_sum[co] * (1.f / 65536.f);
    float var  = g_sqsum[co] * (1.f / 65536.f) - mean * mean;
    float ga = rsqrtf(var + 1e-5f) * gamma[co];
    float be = beta[co];
    float4 v = *(const float4*)&g_y[(size_t)i4 * 4];
    float4 r;
    {
        float x = (v.x - mean) * ga + be;
        float u = 0.7978845608028654f * (x + 0.044715f * x * x * x);
        r.x = 0.5f * x * (1.f + tanh_fast(u));
    }
    {
        float x = (v.y - mean) * ga + be;
        float u = 0.7978845608028654f * (x + 0.044715f * x * x * x);
        r.y = 0.5f * x * (1.f + tanh_fast(u));
    }
    {
        float x = (v.z - mean) * ga + be;
        float u = 0.7978845608028654f * (x + 0.044715f * x * x * x);
        r.z = 0.5f * x * (1.f + tanh_fast(u));
    }
    {
        float x = (v.w - mean) * ga + be;
        float u = 0.7978845608028654f * (x + 0.044715f * x * x * x);
        r.w = 0.5f * x * (1.f + tanh_fast(u));
    }
    *(float4*)&out[(size_t)i4 * 4] = r;
}

// ---------------------------------------------------------------------------
extern "C" void kernel_launch(void* const* d_in, const int* in_sizes, int n_in,
                              void* d_out, int out_size)
{
    const float* sparse_fea = (const float*)d_in[0];
    const float* dense_fea  = (const float*)d_in[1];
    const float* stk_coor   = (const float*)d_in[2];
    const float* conv_w     = (const float*)d_in[3];
    // d_in[4] = conv_b: zeros AND cancels under batch-stat BN.
    const float* bn_gamma   = (const float*)d_in[5];
    const float* bn_beta    = (const float*)d_in[6];
    float* out = (float*)d_out;

    cudaFuncSetAttribute(conv_mma_kernel,
                         cudaFuncAttributeMaxDynamicSharedMemorySize, 68608);

    wprep_kernel<<<256, 192>>>(conv_w);
    fps_kernel<<<64, 64>>>(stk_coor, out + OFF_COOR);
    gather_sparse<<<2048, 256>>>(sparse_fea, out);
    conv_mma_kernel<<<dim3(8, 64), 512, 68608>>>(dense_fea);
    bn_gelu_kernel<<<16384, 256>>>(bn_gamma, bn_beta, out + OFF_DENSE);
}